// round 3
// baseline (speedup 1.0000x reference)
#include <cuda_runtime.h>
#include <math.h>

#define BB   4
#define SS   2048
#define HH   1024
#define NHH  16
#define HDD  64
#define MM   (BB*SS)   /* 8192 tokens */

// ---------------- scratch (device globals: allocation-free) ----------------
__device__ float g_q[(size_t)MM*HH];
__device__ float g_k[(size_t)MM*HH];
__device__ float g_v[(size_t)MM*HH];
__device__ float g_g[(size_t)MM*HH];
__device__ float g_ab[(size_t)MM*2*NHH];
__device__ float g_attn[(size_t)MM*HH];
__device__ float g_z[(size_t)MM*HH];

// ---------------------------------------------------------------------------
// packed f32x2 helpers (sm_100+ PTX; ptxas never auto-generates these)
// ---------------------------------------------------------------------------
typedef unsigned long long ull;
__device__ __forceinline__ ull pk2(float x, float y) {
    ull r; asm("mov.b64 %0, {%1,%2};" : "=l"(r) : "f"(x), "f"(y)); return r;
}
__device__ __forceinline__ ull mul2(ull a, ull b) {
    ull d; asm("mul.rn.f32x2 %0, %1, %2;" : "=l"(d) : "l"(a), "l"(b)); return d;
}
__device__ __forceinline__ ull add2(ull a, ull b) {
    ull d; asm("add.rn.f32x2 %0, %1, %2;" : "=l"(d) : "l"(a), "l"(b)); return d;
}
__device__ __forceinline__ ull fma2(ull a, ull b, ull c) {
    ull d; asm("fma.rn.f32x2 %0, %1, %2, %3;" : "=l"(d) : "l"(a), "l"(b), "l"(c)); return d;
}
__device__ __forceinline__ float2 upk2(ull a) {
    float2 f; asm("mov.b64 {%0,%1}, %2;" : "=f"(f.x), "=f"(f.y) : "l"(a)); return f;
}

__device__ __forceinline__ void cp_async16(void* dst_smem, const void* src_gmem) {
    unsigned dst = (unsigned)__cvta_generic_to_shared(dst_smem);
    asm volatile("cp.async.cg.shared.global [%0], [%1], 16;\n" :: "r"(dst), "l"(src_gmem));
}
__device__ __forceinline__ void cp_async_commit() {
    asm volatile("cp.async.commit_group;\n");
}
__device__ __forceinline__ void cp_async_wait0() {
    asm volatile("cp.async.wait_group 0;\n");
}

// ---------------------------------------------------------------------------
// SGEMM with packed FFMA2: C[M,N] = A[M,K] @ B[N,K]^T, tiles 128x128x8,
// 256 threads, 8x8 per thread held as 8x4 packed f32x2 accumulators.
// Per kk: 8 A-scalar packs (ALU pipe) + 32 fma2 (FMA pipe) — halves the
// FMA-pipe instruction count vs scalar FFMA (which is rt=2 on sm_103a).
// ---------------------------------------------------------------------------
__global__ __launch_bounds__(256) void sgemm_nt(const float* __restrict__ A,
                                                const float* __restrict__ Bm,
                                                float* __restrict__ C,
                                                int K, int N)
{
    const int tid  = threadIdx.x;
    const int tx   = tid & 15;
    const int ty   = tid >> 4;
    const int row0 = blockIdx.y * 128;
    const int col0 = blockIdx.x * 128;

    __shared__ float As[2][8][128];
    __shared__ float Bs[2][8][128];

    const int lr = tid >> 1;
    const int lk = (tid & 1) << 2;
    const float* Ap = A  + (size_t)(row0 + lr) * K + lk;
    const float* Bp = Bm + (size_t)(col0 + lr) * K + lk;

    float4 a4 = *(const float4*)Ap;
    float4 b4 = *(const float4*)Bp;
    As[0][lk+0][lr]=a4.x; As[0][lk+1][lr]=a4.y; As[0][lk+2][lr]=a4.z; As[0][lk+3][lr]=a4.w;
    Bs[0][lk+0][lr]=b4.x; Bs[0][lk+1][lr]=b4.y; Bs[0][lk+2][lr]=b4.z; Bs[0][lk+3][lr]=b4.w;
    __syncthreads();

    ull acc2[8][4];
    #pragma unroll
    for (int i = 0; i < 8; ++i)
        #pragma unroll
        for (int j = 0; j < 4; ++j) acc2[i][j] = 0ull;

    const int nk = K >> 3;
    int buf = 0;

    for (int kt = 0; kt < nk; ++kt) {
        float4 na, nb;
        const bool have_next = (kt + 1 < nk);
        if (have_next) {
            na = *(const float4*)(Ap + (size_t)(kt+1)*8);
            nb = *(const float4*)(Bp + (size_t)(kt+1)*8);
        }
        #pragma unroll
        for (int kk = 0; kk < 8; ++kk) {
            float af[8];
            ull   bf2[4];
            *(float4*)(af)   = *(const float4*)&As[buf][kk][ty*8];
            *(float4*)(af+4) = *(const float4*)&As[buf][kk][ty*8+4];
            {
                const ulonglong2* bp = (const ulonglong2*)&Bs[buf][kk][tx*8];
                ulonglong2 b01 = bp[0];
                ulonglong2 b23 = bp[1];
                bf2[0] = b01.x; bf2[1] = b01.y; bf2[2] = b23.x; bf2[3] = b23.y;
            }
            ull ai2[8];
            #pragma unroll
            for (int i = 0; i < 8; ++i) ai2[i] = pk2(af[i], af[i]);
            #pragma unroll
            for (int i = 0; i < 8; ++i)
                #pragma unroll
                for (int j = 0; j < 4; ++j)
                    acc2[i][j] = fma2(ai2[i], bf2[j], acc2[i][j]);
        }
        if (have_next) {
            const int nb2 = buf ^ 1;
            As[nb2][lk+0][lr]=na.x; As[nb2][lk+1][lr]=na.y; As[nb2][lk+2][lr]=na.z; As[nb2][lk+3][lr]=na.w;
            Bs[nb2][lk+0][lr]=nb.x; Bs[nb2][lk+1][lr]=nb.y; Bs[nb2][lk+2][lr]=nb.z; Bs[nb2][lk+3][lr]=nb.w;
        }
        __syncthreads();
        buf ^= 1;
    }

    #pragma unroll
    for (int i = 0; i < 8; ++i) {
        float* Cp = C + (size_t)(row0 + ty*8 + i) * N + col0 + tx*8;
        float2 c0 = upk2(acc2[i][0]);
        float2 c1 = upk2(acc2[i][1]);
        float2 c2 = upk2(acc2[i][2]);
        float2 c3 = upk2(acc2[i][3]);
        *(float4*)(Cp)   = make_float4(c0.x, c0.y, c1.x, c1.y);
        *(float4*)(Cp+4) = make_float4(c2.x, c2.y, c3.x, c3.y);
    }
}

// ---------------------------------------------------------------------------
// alpha/beta: 8 tokens per block, weight rows register-resident per warp.
// layout: g_ab[m*32 + o] = sigmoid(x_m @ W_o + b_o), o<16 -> alpha, o>=16 -> beta
// ---------------------------------------------------------------------------
__global__ __launch_bounds__(256) void ab_kernel(const float* __restrict__ x,
                                                 const float* __restrict__ Wa,
                                                 const float* __restrict__ ba,
                                                 const float* __restrict__ Wb,
                                                 const float* __restrict__ bb,
                                                 float* __restrict__ ab)
{
    const int m0  = blockIdx.x * 8;
    const int tid = threadIdx.x;
    __shared__ float xs[8][HH];

    for (int n = tid; n < 8 * HH / 4; n += 256) {
        const int tok = n / (HH/4);
        const int e4  = (n % (HH/4)) * 4;
        *(float4*)&xs[tok][e4] = *(const float4*)&x[(size_t)(m0 + tok)*HH + e4];
    }
    __syncthreads();

    const int warp = tid >> 5, lane = tid & 31;
    for (int o = warp; o < 32; o += 8) {
        const float* w = (o < 16) ? (Wa + (size_t)o*HH) : (Wb + (size_t)(o-16)*HH);
        float wr[32];
        #pragma unroll
        for (int u = 0; u < 32; ++u) wr[u] = w[lane + u*32];
        const float bias = (o < 16) ? ba[o] : bb[o-16];
        for (int tok = 0; tok < 8; ++tok) {
            float sum = 0.f;
            #pragma unroll
            for (int u = 0; u < 32; ++u)
                sum = fmaf(wr[u], xs[tok][lane + u*32], sum);
            #pragma unroll
            for (int off = 16; off; off >>= 1)
                sum += __shfl_xor_sync(0xffffffffu, sum, off);
            if (lane == 0) {
                float y = sum + bias;
                ab[(size_t)(m0 + tok)*32 + o] = 1.f / (1.f + expf(-y));
            }
        }
    }
}

// ---------------------------------------------------------------------------
// activations: l2-normalize q and k per (token,head); silu(v) in place.
// ---------------------------------------------------------------------------
__global__ __launch_bounds__(256) void act_kernel(float* __restrict__ q,
                                                  float* __restrict__ k,
                                                  float* __restrict__ v)
{
    const int g    = blockIdx.x * 8 + (threadIdx.x >> 5);
    const int lane = threadIdx.x & 31;
    const size_t base = (size_t)g * HDD;

    {
        float a0 = q[base + lane], a1 = q[base + lane + 32];
        float ss = a0*a0 + a1*a1;
        #pragma unroll
        for (int off = 16; off; off >>= 1) ss += __shfl_xor_sync(0xffffffffu, ss, off);
        float inv = 1.f / fmaxf(sqrtf(ss), 1e-12f);
        q[base + lane] = a0 * inv;  q[base + lane + 32] = a1 * inv;
    }
    {
        float a0 = k[base + lane], a1 = k[base + lane + 32];
        float ss = a0*a0 + a1*a1;
        #pragma unroll
        for (int off = 16; off; off >>= 1) ss += __shfl_xor_sync(0xffffffffu, ss, off);
        float inv = 1.f / fmaxf(sqrtf(ss), 1e-12f);
        k[base + lane] = a0 * inv;  k[base + lane + 32] = a1 * inv;
    }
    {
        float a0 = v[base + lane], a1 = v[base + lane + 32];
        v[base + lane]      = a0 / (1.f + expf(-a0));
        v[base + lane + 32] = a1 / (1.f + expf(-a1));
    }
}

// ---------------------------------------------------------------------------
// Sequential scan, tile-staged (unchanged from R2).
// ---------------------------------------------------------------------------
#define TILE 16
#define NTILE (SS/TILE)

__global__ __launch_bounds__(256) void scan_kernel(const float* __restrict__ q,
                                                   const float* __restrict__ k,
                                                   const float* __restrict__ v,
                                                   const float* __restrict__ ab,
                                                   float* __restrict__ attn)
{
    const int bh  = blockIdx.x;
    const int b   = bh >> 4;
    const int h   = bh & 15;
    const int tid = threadIdx.x;
    const int i   = tid >> 2;   // state row 0..63
    const int c   = tid & 3;    // col group 0..3

    __shared__ float sk[2][TILE][64];
    __shared__ float sv[2][TILE][64];
    __shared__ float sq[2][TILE][64];
    __shared__ float sab[SS][2];

    auto base = [&](int t) { return ((size_t)(b*SS + t) * HH + (size_t)h*HDD); };

    {
        const int tt = tid >> 4;
        const int e4 = (tid & 15) << 2;
        cp_async16(&sk[0][tt][e4], k + base(tt) + e4);
        cp_async16(&sv[0][tt][e4], v + base(tt) + e4);
        cp_async16(&sq[0][tt][e4], q + base(tt) + e4);
        cp_async_commit();
    }
    for (int t = tid; t < SS; t += 256) {
        const size_t o = (size_t)(b*SS + t) * 32;
        sab[t][0] = ab[o + h];
        sab[t][1] = ab[o + 16 + h];
    }
    cp_async_wait0();
    __syncthreads();

    ull s2[8];
    #pragma unroll
    for (int j = 0; j < 8; ++j) s2[j] = 0ull;

    int buf = 0;
    for (int tile = 0; tile < NTILE; ++tile) {
        const int t0 = tile * TILE;
        if (tile + 1 < NTILE) {
            const int nx = buf ^ 1;
            const int tt = tid >> 4;
            const int e4 = (tid & 15) << 2;
            const size_t nb = base(t0 + TILE + tt) + e4;
            cp_async16(&sk[nx][tt][e4], k + nb);
            cp_async16(&sv[nx][tt][e4], v + nb);
            cp_async16(&sq[nx][tt][e4], q + nb);
            cp_async_commit();
        }

        #pragma unroll 4
        for (int tt = 0; tt < TILE; ++tt) {
            const int t = t0 + tt;
            const float2 abv = *(const float2*)&sab[t][0];
            const float a  = abv.x;
            const float be = abv.y;
            const float ki = sk[buf][tt][i];
            const float vi = sv[buf][tt][i];

            const ull a2   = pk2(a, a);
            const ull be2  = pk2(be, be);
            const ull vi2  = pk2(vi, vi);
            const ull nki2 = pk2(-ki, -ki);

            ull k2[8], q2[8];
            {
                const ulonglong2* kp = (const ulonglong2*)&sk[buf][tt][c*16];
                const ulonglong2* qp = (const ulonglong2*)&sq[buf][tt][c*16];
                #pragma unroll
                for (int w = 0; w < 4; ++w) {
                    ulonglong2 kk = kp[w]; k2[w*2] = kk.x; k2[w*2+1] = kk.y;
                    ulonglong2 qq = qp[w]; q2[w*2] = qq.x; q2[w*2+1] = qq.y;
                }
            }

            ull pa = 0ull, pb = 0ull;
            #pragma unroll
            for (int j = 0; j < 8; ++j) {
                const ull w2  = mul2(be2, k2[j]);
                const ull r   = mul2(a2, s2[j]);
                const ull tmp = fma2(nki2, r, vi2);
                s2[j] = fma2(w2, tmp, r);
                if (j & 1) pb = fma2(s2[j], q2[j], pb);
                else       pa = fma2(s2[j], q2[j], pa);
            }
            const float2 ps = upk2(add2(pa, pb));
            float partial = ps.x + ps.y;
            partial += __shfl_xor_sync(0xffffffffu, partial, 1);
            partial += __shfl_xor_sync(0xffffffffu, partial, 2);
            if (c == 0) attn[base(t) + i] = partial;
        }

        if (tile + 1 < NTILE) cp_async_wait0();
        __syncthreads();
        buf ^= 1;
    }
}

// ---------------------------------------------------------------------------
// layernorm over H + gate
// ---------------------------------------------------------------------------
__global__ __launch_bounds__(256) void ln_gate_kernel(const float* __restrict__ attn,
                                                      const float* __restrict__ gate,
                                                      const float* __restrict__ ln_g,
                                                      const float* __restrict__ ln_b,
                                                      float* __restrict__ z)
{
    const int m   = blockIdx.x;
    const int tid = threadIdx.x;
    const size_t rb = (size_t)m * HH + tid*4;

    float4 xv = *(const float4*)&attn[rb];
    float s  = xv.x + xv.y + xv.z + xv.w;
    float ss = xv.x*xv.x + xv.y*xv.y + xv.z*xv.z + xv.w*xv.w;
    #pragma unroll
    for (int off = 16; off; off >>= 1) {
        s  += __shfl_xor_sync(0xffffffffu, s,  off);
        ss += __shfl_xor_sync(0xffffffffu, ss, off);
    }
    __shared__ float rs[8], rss[8];
    if ((tid & 31) == 0) { rs[tid>>5] = s; rss[tid>>5] = ss; }
    __syncthreads();
    float tot = 0.f, tots = 0.f;
    #pragma unroll
    for (int w = 0; w < 8; ++w) { tot += rs[w]; tots += rss[w]; }

    const float mean = tot * (1.f/HH);
    const float var  = tots * (1.f/HH) - mean*mean;
    const float inv  = rsqrtf(var + 1e-5f);

    float4 gv = *(const float4*)&gate[rb];
    float4 lg = *(const float4*)&ln_g[tid*4];
    float4 lb = *(const float4*)&ln_b[tid*4];

    float4 o;
    o.x = ((xv.x-mean)*inv*lg.x + lb.x) * (gv.x / (1.f + expf(-gv.x)));
    o.y = ((xv.y-mean)*inv*lg.y + lb.y) * (gv.y / (1.f + expf(-gv.y)));
    o.z = ((xv.z-mean)*inv*lg.z + lb.z) * (gv.z / (1.f + expf(-gv.z)));
    o.w = ((xv.w-mean)*inv*lg.w + lb.w) * (gv.w / (1.f + expf(-gv.w)));
    *(float4*)&z[rb] = o;
}

// ---------------------------------------------------------------------------
extern "C" void kernel_launch(void* const* d_in, const int* in_sizes, int n_in,
                              void* d_out, int out_size)
{
    const float* x    = (const float*)d_in[0];
    const float* Wq   = (const float*)d_in[1];
    const float* Wk   = (const float*)d_in[2];
    const float* Wv   = (const float*)d_in[3];
    const float* Wa   = (const float*)d_in[4];
    const float* ba   = (const float*)d_in[5];
    const float* Wb   = (const float*)d_in[6];
    const float* bb   = (const float*)d_in[7];
    const float* Wg   = (const float*)d_in[8];
    const float* Wo   = (const float*)d_in[9];
    const float* ln_g = (const float*)d_in[10];
    const float* ln_b = (const float*)d_in[11];
    float* out = (float*)d_out;

    float *qp, *kp, *vp, *gp, *abp, *attnp, *zp;
    cudaGetSymbolAddress((void**)&qp,    g_q);
    cudaGetSymbolAddress((void**)&kp,    g_k);
    cudaGetSymbolAddress((void**)&vp,    g_v);
    cudaGetSymbolAddress((void**)&gp,    g_g);
    cudaGetSymbolAddress((void**)&abp,   g_ab);
    cudaGetSymbolAddress((void**)&attnp, g_attn);
    cudaGetSymbolAddress((void**)&zp,    g_z);

    dim3 grid_g(HH/128, MM/128);   // (8, 64)

    sgemm_nt<<<grid_g, 256>>>(x, Wq, qp, HH, HH);
    sgemm_nt<<<grid_g, 256>>>(x, Wk, kp, HH, HH);
    sgemm_nt<<<grid_g, 256>>>(x, Wv, vp, HH, HH);
    sgemm_nt<<<grid_g, 256>>>(x, Wg, gp, HH, HH);

    ab_kernel<<<MM/8, 256>>>(x, Wa, ba, Wb, bb, abp);
    act_kernel<<<(MM*NHH)/8, 256>>>(qp, kp, vp);

    scan_kernel<<<BB*NHH, 256>>>(qp, kp, vp, abp, attnp);

    ln_gate_kernel<<<MM, 256>>>(attnp, gp, ln_g, ln_b, zp);

    sgemm_nt<<<grid_g, 256>>>(zp, Wo, out, HH, HH);
}

// round 5
// speedup vs baseline: 2.4215x; 2.4215x over previous
#include <cuda_runtime.h>
#include <math.h>

#define BB   4
#define SS   2048
#define HH   1024
#define NHH  16
#define HDD  64
#define MM   (BB*SS)   /* 8192 tokens */

// ---------------- scratch (device globals: allocation-free) ----------------
__device__ float g_q[(size_t)MM*HH];
__device__ float g_k[(size_t)MM*HH];
__device__ float g_v[(size_t)MM*HH];
__device__ float g_g[(size_t)MM*HH];
__device__ float g_ab[(size_t)MM*2*NHH];
__device__ float g_attn[(size_t)MM*HH];
__device__ float g_z[(size_t)MM*HH];
__device__ float g_xr[(size_t)MM*HH];        // tf32-rounded x
__device__ float g_wr[(size_t)5*HH*HH];      // tf32-rounded Wq,Wk,Wv,Wg,Wo

// ---------------------------------------------------------------------------
// packed f32x2 helpers (scan kernel)
// ---------------------------------------------------------------------------
typedef unsigned long long ull;
__device__ __forceinline__ ull pk2(float x, float y) {
    ull r; asm("mov.b64 %0, {%1,%2};" : "=l"(r) : "f"(x), "f"(y)); return r;
}
__device__ __forceinline__ ull mul2(ull a, ull b) {
    ull d; asm("mul.rn.f32x2 %0, %1, %2;" : "=l"(d) : "l"(a), "l"(b)); return d;
}
__device__ __forceinline__ ull add2(ull a, ull b) {
    ull d; asm("add.rn.f32x2 %0, %1, %2;" : "=l"(d) : "l"(a), "l"(b)); return d;
}
__device__ __forceinline__ ull fma2(ull a, ull b, ull c) {
    ull d; asm("fma.rn.f32x2 %0, %1, %2, %3;" : "=l"(d) : "l"(a), "l"(b), "l"(c)); return d;
}
__device__ __forceinline__ float2 upk2(ull a) {
    float2 f; asm("mov.b64 {%0,%1}, %2;" : "=f"(f.x), "=f"(f.y) : "l"(a)); return f;
}

__device__ __forceinline__ void cp_async16(void* dst_smem, const void* src_gmem) {
    unsigned dst = (unsigned)__cvta_generic_to_shared(dst_smem);
    asm volatile("cp.async.cg.shared.global [%0], [%1], 16;\n" :: "r"(dst), "l"(src_gmem));
}
__device__ __forceinline__ void cp_async_commit() {
    asm volatile("cp.async.commit_group;\n");
}
__device__ __forceinline__ void cp_async_wait0() {
    asm volatile("cp.async.wait_group 0;\n");
}

__device__ __forceinline__ float to_tf32(float x) {
    unsigned u; asm("cvt.rna.tf32.f32 %0, %1;" : "=r"(u) : "f"(x));
    return __uint_as_float(u);
}

// ---------------------------------------------------------------------------
// tf32 tensor-core GEMM via mma.sync (baseline PTX, works on compute_103):
// C[M,N] = A[M,K] @ B[N,K]^T.  Block tile 128x128, K-chunks of 32, 3-stage
// cp.async ring. 8 warps: warp (wm, wn) = (wid&1, wid>>1) computes 64x32.
// Shared tiles padded to stride 36 floats -> conflict-free fragment loads.
// ---------------------------------------------------------------------------
#define GS      3
#define CHK     32
#define NCHK    (HH/CHK)        /* 32 */
#define LDA     36              /* floats per shared row */
#define TILE_FL (128*LDA)       /* 4608 floats per tile */
#define STG_FL  (2*TILE_FL)     /* A+B per stage */
#define GSMEM_SZ (GS*STG_FL*4)  /* 110592 bytes */

__device__ __forceinline__ void mma_tf32(float* c, const unsigned* a, const unsigned* b) {
    asm volatile(
        "mma.sync.aligned.m16n8k8.row.col.f32.tf32.tf32.f32 "
        "{%0,%1,%2,%3}, {%4,%5,%6,%7}, {%8,%9}, {%0,%1,%2,%3};"
        : "+f"(c[0]), "+f"(c[1]), "+f"(c[2]), "+f"(c[3])
        : "r"(a[0]), "r"(a[1]), "r"(a[2]), "r"(a[3]), "r"(b[0]), "r"(b[1]));
}

__device__ __forceinline__ void load_chunk_g(const float* __restrict__ A,
                                             const float* __restrict__ Bm,
                                             float* sm, int stage,
                                             int row0, int col0, int kbase, int tid)
{
    float* sa = sm + stage*STG_FL;
    float* sb = sa + TILE_FL;
    #pragma unroll
    for (int it = 0; it < 4; ++it) {
        const int n   = tid + it*256;     // 0..1023
        const int row = n >> 3;           // 0..127
        const int fc  = (n & 7) << 2;     // 0,4,...,28
        cp_async16(sa + row*LDA + fc, A  + (size_t)(row0 + row)*HH + kbase + fc);
        cp_async16(sb + row*LDA + fc, Bm + (size_t)(col0 + row)*HH + kbase + fc);
    }
    cp_async_commit();
}

__global__ __launch_bounds__(256) void gemm_tf32(const float* __restrict__ A,
                                                 const float* __restrict__ Bm,
                                                 float* __restrict__ C)
{
    extern __shared__ float sm[];
    const int tid  = threadIdx.x;
    const int wid  = tid >> 5;
    const int lane = tid & 31;
    const int wm   = wid & 1;          // 0..1  (m)
    const int wn   = wid >> 1;         // 0..3  (n)
    const int l4   = lane >> 2;        // 0..7
    const int lm   = lane & 3;         // 0..3
    const int row0 = blockIdx.y * 128;
    const int col0 = blockIdx.x * 128;

    float acc[4][4][4];
    #pragma unroll
    for (int mt = 0; mt < 4; ++mt)
        #pragma unroll
        for (int nt = 0; nt < 4; ++nt)
            #pragma unroll
            for (int r = 0; r < 4; ++r) acc[mt][nt][r] = 0.f;

    // prologue: stage chunks 0..GS-2
    load_chunk_g(A, Bm, sm, 0, row0, col0, 0*CHK, tid);
    load_chunk_g(A, Bm, sm, 1, row0, col0, 1*CHK, tid);

    for (int c = 0; c < NCHK; ++c) {
        if (c + GS - 1 < NCHK)
            load_chunk_g(A, Bm, sm, (c + GS - 1) % GS, row0, col0, (c + GS - 1)*CHK, tid);

        if (c < NCHK - 2)       asm volatile("cp.async.wait_group 2;");
        else if (c == NCHK - 2) asm volatile("cp.async.wait_group 1;");
        else                    asm volatile("cp.async.wait_group 0;");
        __syncthreads();

        const float* sa = sm + (c % GS)*STG_FL;
        const float* sb = sa + TILE_FL;

        #pragma unroll
        for (int ks = 0; ks < 4; ++ks) {
            const int kk = ks*8;
            unsigned a[4][4], b[4][2];
            #pragma unroll
            for (int mt = 0; mt < 4; ++mt) {
                const float* ap = sa + (wm*64 + mt*16 + l4)*LDA + kk + lm;
                a[mt][0] = __float_as_uint(ap[0]);
                a[mt][1] = __float_as_uint(ap[8*LDA]);
                a[mt][2] = __float_as_uint(ap[4]);
                a[mt][3] = __float_as_uint(ap[8*LDA + 4]);
            }
            #pragma unroll
            for (int nt = 0; nt < 4; ++nt) {
                const float* bp = sb + (wn*32 + nt*8 + l4)*LDA + kk + lm;
                b[nt][0] = __float_as_uint(bp[0]);
                b[nt][1] = __float_as_uint(bp[4]);
            }
            #pragma unroll
            for (int mt = 0; mt < 4; ++mt)
                #pragma unroll
                for (int nt = 0; nt < 4; ++nt)
                    mma_tf32(acc[mt][nt], a[mt], b[nt]);
        }
        __syncthreads();
    }

    // epilogue: c0,c1 at (row, col*2..+1); c2,c3 at (row+8, ...)
    #pragma unroll
    for (int mt = 0; mt < 4; ++mt) {
        const int rg = row0 + wm*64 + mt*16 + l4;
        #pragma unroll
        for (int nt = 0; nt < 4; ++nt) {
            const int cg = col0 + wn*32 + nt*8 + lm*2;
            float* p = C + (size_t)rg*HH + cg;
            *(float2*)p            = make_float2(acc[mt][nt][0], acc[mt][nt][1]);
            *(float2*)(p + 8*HH)   = make_float2(acc[mt][nt][2], acc[mt][nt][3]);
        }
    }
}

// ---------------------------------------------------------------------------
// tf32 pre-rounding (RNA, unbiased) — 1 float4 per thread
// ---------------------------------------------------------------------------
__global__ __launch_bounds__(256) void round_kernel(const float* __restrict__ in,
                                                    float* __restrict__ out)
{
    const size_t i = (size_t)blockIdx.x * 256 + threadIdx.x;
    float4 v = ((const float4*)in)[i];
    v.x = to_tf32(v.x); v.y = to_tf32(v.y);
    v.z = to_tf32(v.z); v.w = to_tf32(v.w);
    ((float4*)out)[i] = v;
}

// ---------------------------------------------------------------------------
// alpha/beta: 8 tokens per block, weight rows register-resident per warp.
// ---------------------------------------------------------------------------
__global__ __launch_bounds__(256) void ab_kernel(const float* __restrict__ x,
                                                 const float* __restrict__ Wa,
                                                 const float* __restrict__ ba,
                                                 const float* __restrict__ Wb,
                                                 const float* __restrict__ bb,
                                                 float* __restrict__ ab)
{
    const int m0  = blockIdx.x * 8;
    const int tid = threadIdx.x;
    __shared__ float xs[8][HH];

    for (int n = tid; n < 8 * HH / 4; n += 256) {
        const int tok = n / (HH/4);
        const int e4  = (n % (HH/4)) * 4;
        *(float4*)&xs[tok][e4] = *(const float4*)&x[(size_t)(m0 + tok)*HH + e4];
    }
    __syncthreads();

    const int warp = tid >> 5, lane = tid & 31;
    for (int o = warp; o < 32; o += 8) {
        const float* w = (o < 16) ? (Wa + (size_t)o*HH) : (Wb + (size_t)(o-16)*HH);
        float wr[32];
        #pragma unroll
        for (int u = 0; u < 32; ++u) wr[u] = w[lane + u*32];
        const float bias = (o < 16) ? ba[o] : bb[o-16];
        for (int tok = 0; tok < 8; ++tok) {
            float sum = 0.f;
            #pragma unroll
            for (int u = 0; u < 32; ++u)
                sum = fmaf(wr[u], xs[tok][lane + u*32], sum);
            #pragma unroll
            for (int off = 16; off; off >>= 1)
                sum += __shfl_xor_sync(0xffffffffu, sum, off);
            if (lane == 0) {
                float y = sum + bias;
                ab[(size_t)(m0 + tok)*32 + o] = 1.f / (1.f + expf(-y));
            }
        }
    }
}

// ---------------------------------------------------------------------------
// activations: l2-normalize q and k per (token,head); silu(v) in place.
// ---------------------------------------------------------------------------
__global__ __launch_bounds__(256) void act_kernel(float* __restrict__ q,
                                                  float* __restrict__ k,
                                                  float* __restrict__ v)
{
    const int g    = blockIdx.x * 8 + (threadIdx.x >> 5);
    const int lane = threadIdx.x & 31;
    const size_t base = (size_t)g * HDD;

    {
        float a0 = q[base + lane], a1 = q[base + lane + 32];
        float ss = a0*a0 + a1*a1;
        #pragma unroll
        for (int off = 16; off; off >>= 1) ss += __shfl_xor_sync(0xffffffffu, ss, off);
        float inv = 1.f / fmaxf(sqrtf(ss), 1e-12f);
        q[base + lane] = a0 * inv;  q[base + lane + 32] = a1 * inv;
    }
    {
        float a0 = k[base + lane], a1 = k[base + lane + 32];
        float ss = a0*a0 + a1*a1;
        #pragma unroll
        for (int off = 16; off; off >>= 1) ss += __shfl_xor_sync(0xffffffffu, ss, off);
        float inv = 1.f / fmaxf(sqrtf(ss), 1e-12f);
        k[base + lane] = a0 * inv;  k[base + lane + 32] = a1 * inv;
    }
    {
        float a0 = v[base + lane], a1 = v[base + lane + 32];
        v[base + lane]      = a0 / (1.f + expf(-a0));
        v[base + lane + 32] = a1 / (1.f + expf(-a1));
    }
}

// ---------------------------------------------------------------------------
// Sequential scan, tile-staged (unchanged).
// ---------------------------------------------------------------------------
#define TILE 16
#define NTILE (SS/TILE)

__global__ __launch_bounds__(256) void scan_kernel(const float* __restrict__ q,
                                                   const float* __restrict__ k,
                                                   const float* __restrict__ v,
                                                   const float* __restrict__ ab,
                                                   float* __restrict__ attn)
{
    const int bh  = blockIdx.x;
    const int b   = bh >> 4;
    const int h   = bh & 15;
    const int tid = threadIdx.x;
    const int i   = tid >> 2;   // state row 0..63
    const int c   = tid & 3;    // col group 0..3

    __shared__ float sk[2][TILE][64];
    __shared__ float sv[2][TILE][64];
    __shared__ float sq[2][TILE][64];
    __shared__ float sab[SS][2];

    auto base = [&](int t) { return ((size_t)(b*SS + t) * HH + (size_t)h*HDD); };

    {
        const int tt = tid >> 4;
        const int e4 = (tid & 15) << 2;
        cp_async16(&sk[0][tt][e4], k + base(tt) + e4);
        cp_async16(&sv[0][tt][e4], v + base(tt) + e4);
        cp_async16(&sq[0][tt][e4], q + base(tt) + e4);
        cp_async_commit();
    }
    for (int t = tid; t < SS; t += 256) {
        const size_t o = (size_t)(b*SS + t) * 32;
        sab[t][0] = ab[o + h];
        sab[t][1] = ab[o + 16 + h];
    }
    cp_async_wait0();
    __syncthreads();

    ull s2[8];
    #pragma unroll
    for (int j = 0; j < 8; ++j) s2[j] = 0ull;

    int buf = 0;
    for (int tile = 0; tile < NTILE; ++tile) {
        const int t0 = tile * TILE;
        if (tile + 1 < NTILE) {
            const int nx = buf ^ 1;
            const int tt = tid >> 4;
            const int e4 = (tid & 15) << 2;
            const size_t nb = base(t0 + TILE + tt) + e4;
            cp_async16(&sk[nx][tt][e4], k + nb);
            cp_async16(&sv[nx][tt][e4], v + nb);
            cp_async16(&sq[nx][tt][e4], q + nb);
            cp_async_commit();
        }

        #pragma unroll 4
        for (int tt = 0; tt < TILE; ++tt) {
            const int t = t0 + tt;
            const float2 abv = *(const float2*)&sab[t][0];
            const float a  = abv.x;
            const float be = abv.y;
            const float ki = sk[buf][tt][i];
            const float vi = sv[buf][tt][i];

            const ull a2   = pk2(a, a);
            const ull be2  = pk2(be, be);
            const ull vi2  = pk2(vi, vi);
            const ull nki2 = pk2(-ki, -ki);

            ull k2[8], q2[8];
            {
                const ulonglong2* kp = (const ulonglong2*)&sk[buf][tt][c*16];
                const ulonglong2* qp = (const ulonglong2*)&sq[buf][tt][c*16];
                #pragma unroll
                for (int w = 0; w < 4; ++w) {
                    ulonglong2 kk = kp[w]; k2[w*2] = kk.x; k2[w*2+1] = kk.y;
                    ulonglong2 qq = qp[w]; q2[w*2] = qq.x; q2[w*2+1] = qq.y;
                }
            }

            ull pa = 0ull, pb = 0ull;
            #pragma unroll
            for (int j = 0; j < 8; ++j) {
                const ull w2  = mul2(be2, k2[j]);
                const ull r   = mul2(a2, s2[j]);
                const ull tmp = fma2(nki2, r, vi2);
                s2[j] = fma2(w2, tmp, r);
                if (j & 1) pb = fma2(s2[j], q2[j], pb);
                else       pa = fma2(s2[j], q2[j], pa);
            }
            const float2 ps = upk2(add2(pa, pb));
            float partial = ps.x + ps.y;
            partial += __shfl_xor_sync(0xffffffffu, partial, 1);
            partial += __shfl_xor_sync(0xffffffffu, partial, 2);
            if (c == 0) attn[base(t) + i] = partial;
        }

        if (tile + 1 < NTILE) cp_async_wait0();
        __syncthreads();
        buf ^= 1;
    }
}

// ---------------------------------------------------------------------------
// layernorm over H + gate; output pre-rounded to tf32 (feeds the Wo GEMM)
// ---------------------------------------------------------------------------
__global__ __launch_bounds__(256) void ln_gate_kernel(const float* __restrict__ attn,
                                                      const float* __restrict__ gate,
                                                      const float* __restrict__ ln_g,
                                                      const float* __restrict__ ln_b,
                                                      float* __restrict__ z)
{
    const int m   = blockIdx.x;
    const int tid = threadIdx.x;
    const size_t rb = (size_t)m * HH + tid*4;

    float4 xv = *(const float4*)&attn[rb];
    float s  = xv.x + xv.y + xv.z + xv.w;
    float ss = xv.x*xv.x + xv.y*xv.y + xv.z*xv.z + xv.w*xv.w;
    #pragma unroll
    for (int off = 16; off; off >>= 1) {
        s  += __shfl_xor_sync(0xffffffffu, s,  off);
        ss += __shfl_xor_sync(0xffffffffu, ss, off);
    }
    __shared__ float rs[8], rss[8];
    if ((tid & 31) == 0) { rs[tid>>5] = s; rss[tid>>5] = ss; }
    __syncthreads();
    float tot = 0.f, tots = 0.f;
    #pragma unroll
    for (int w = 0; w < 8; ++w) { tot += rs[w]; tots += rss[w]; }

    const float mean = tot * (1.f/HH);
    const float var  = tots * (1.f/HH) - mean*mean;
    const float inv  = rsqrtf(var + 1e-5f);

    float4 gv = *(const float4*)&gate[rb];
    float4 lg = *(const float4*)&ln_g[tid*4];
    float4 lb = *(const float4*)&ln_b[tid*4];

    float4 o;
    o.x = to_tf32(((xv.x-mean)*inv*lg.x + lb.x) * (gv.x / (1.f + expf(-gv.x))));
    o.y = to_tf32(((xv.y-mean)*inv*lg.y + lb.y) * (gv.y / (1.f + expf(-gv.y))));
    o.z = to_tf32(((xv.z-mean)*inv*lg.z + lb.z) * (gv.z / (1.f + expf(-gv.z))));
    o.w = to_tf32(((xv.w-mean)*inv*lg.w + lb.w) * (gv.w / (1.f + expf(-gv.w))));
    *(float4*)&z[rb] = o;
}

// ---------------------------------------------------------------------------
extern "C" void kernel_launch(void* const* d_in, const int* in_sizes, int n_in,
                              void* d_out, int out_size)
{
    const float* x    = (const float*)d_in[0];
    const float* Wq   = (const float*)d_in[1];
    const float* Wk   = (const float*)d_in[2];
    const float* Wv   = (const float*)d_in[3];
    const float* Wa   = (const float*)d_in[4];
    const float* ba   = (const float*)d_in[5];
    const float* Wb   = (const float*)d_in[6];
    const float* bb   = (const float*)d_in[7];
    const float* Wg   = (const float*)d_in[8];
    const float* Wo   = (const float*)d_in[9];
    const float* ln_g = (const float*)d_in[10];
    const float* ln_b = (const float*)d_in[11];
    float* out = (float*)d_out;

    float *qp, *kp, *vp, *gp, *abp, *attnp, *zp, *xrp, *wrp;
    cudaGetSymbolAddress((void**)&qp,    g_q);
    cudaGetSymbolAddress((void**)&kp,    g_k);
    cudaGetSymbolAddress((void**)&vp,    g_v);
    cudaGetSymbolAddress((void**)&gp,    g_g);
    cudaGetSymbolAddress((void**)&abp,   g_ab);
    cudaGetSymbolAddress((void**)&attnp, g_attn);
    cudaGetSymbolAddress((void**)&zp,    g_z);
    cudaGetSymbolAddress((void**)&xrp,   g_xr);
    cudaGetSymbolAddress((void**)&wrp,   g_wr);

    float* wq_r = wrp + 0*(size_t)HH*HH;
    float* wk_r = wrp + 1*(size_t)HH*HH;
    float* wv_r = wrp + 2*(size_t)HH*HH;
    float* wg_r = wrp + 3*(size_t)HH*HH;
    float* wo_r = wrp + 4*(size_t)HH*HH;

    cudaFuncSetAttribute(gemm_tf32, cudaFuncAttributeMaxDynamicSharedMemorySize, GSMEM_SZ);

    // pre-round inputs to tf32 (RNA — kills truncation bias)
    round_kernel<<<(MM*HH)/(4*256), 256>>>(x,  xrp);
    round_kernel<<<(HH*HH)/(4*256), 256>>>(Wq, wq_r);
    round_kernel<<<(HH*HH)/(4*256), 256>>>(Wk, wk_r);
    round_kernel<<<(HH*HH)/(4*256), 256>>>(Wv, wv_r);
    round_kernel<<<(HH*HH)/(4*256), 256>>>(Wg, wg_r);
    round_kernel<<<(HH*HH)/(4*256), 256>>>(Wo, wo_r);

    dim3 grid_g(HH/128, MM/128);   // (8, 64)

    gemm_tf32<<<grid_g, 256, GSMEM_SZ>>>(xrp, wq_r, qp);
    gemm_tf32<<<grid_g, 256, GSMEM_SZ>>>(xrp, wk_r, kp);
    gemm_tf32<<<grid_g, 256, GSMEM_SZ>>>(xrp, wv_r, vp);
    gemm_tf32<<<grid_g, 256, GSMEM_SZ>>>(xrp, wg_r, gp);

    ab_kernel<<<MM/8, 256>>>(x, Wa, ba, Wb, bb, abp);
    act_kernel<<<(MM*NHH)/8, 256>>>(qp, kp, vp);

    scan_kernel<<<BB*NHH, 256>>>(qp, kp, vp, abp, attnp);

    ln_gate_kernel<<<MM, 256>>>(attnp, gp, ln_g, ln_b, zp);

    gemm_tf32<<<grid_g, 256, GSMEM_SZ>>>(zp, wo_r, out);
}

// round 6
// speedup vs baseline: 2.9758x; 1.2289x over previous
#include <cuda_runtime.h>
#include <math.h>

#define BB   4
#define SS   2048
#define HH   1024
#define NHH  16
#define HDD  64
#define MM   (BB*SS)   /* 8192 tokens */

// ---------------- scratch (device globals: allocation-free) ----------------
__device__ float g_q[(size_t)MM*HH];
__device__ float g_k[(size_t)MM*HH];
__device__ float g_v[(size_t)MM*HH];
__device__ float g_g[(size_t)MM*HH];
__device__ float g_ab[(size_t)MM*2*NHH];
__device__ float g_attn[(size_t)MM*HH];
__device__ float g_z[(size_t)MM*HH];
__device__ float g_xr[(size_t)MM*HH];        // tf32-rounded x
__device__ float g_wr[(size_t)5*HH*HH];      // tf32-rounded Wq,Wk,Wv,Wg,Wo

// ---------------------------------------------------------------------------
// packed f32x2 helpers (scan kernel)
// ---------------------------------------------------------------------------
typedef unsigned long long ull;
__device__ __forceinline__ ull pk2(float x, float y) {
    ull r; asm("mov.b64 %0, {%1,%2};" : "=l"(r) : "f"(x), "f"(y)); return r;
}
__device__ __forceinline__ ull mul2(ull a, ull b) {
    ull d; asm("mul.rn.f32x2 %0, %1, %2;" : "=l"(d) : "l"(a), "l"(b)); return d;
}
__device__ __forceinline__ ull add2(ull a, ull b) {
    ull d; asm("add.rn.f32x2 %0, %1, %2;" : "=l"(d) : "l"(a), "l"(b)); return d;
}
__device__ __forceinline__ ull fma2(ull a, ull b, ull c) {
    ull d; asm("fma.rn.f32x2 %0, %1, %2, %3;" : "=l"(d) : "l"(a), "l"(b), "l"(c)); return d;
}
__device__ __forceinline__ float2 upk2(ull a) {
    float2 f; asm("mov.b64 {%0,%1}, %2;" : "=f"(f.x), "=f"(f.y) : "l"(a)); return f;
}

__device__ __forceinline__ void cp_async16(void* dst_smem, const void* src_gmem) {
    unsigned dst = (unsigned)__cvta_generic_to_shared(dst_smem);
    asm volatile("cp.async.cg.shared.global [%0], [%1], 16;\n" :: "r"(dst), "l"(src_gmem));
}
__device__ __forceinline__ void cp_async_commit() {
    asm volatile("cp.async.commit_group;\n");
}
__device__ __forceinline__ void cp_async_wait0() {
    asm volatile("cp.async.wait_group 0;\n");
}

__device__ __forceinline__ float to_tf32(float x) {
    unsigned u; asm("cvt.rna.tf32.f32 %0, %1;" : "=r"(u) : "f"(x));
    return __uint_as_float(u);
}

// ---------------------------------------------------------------------------
// tf32 tensor-core GEMM via mma.sync: C[M,N] = A[M,K] @ B[N,K]^T.
// Block tile 128x128, K-chunks of 32, 3-stage cp.async ring, 8 warps (2m x 4n),
// warp tile 64x32 = 4x4 m16n8k8. Shared stride 36 -> conflict-free frag loads.
// ---------------------------------------------------------------------------
#define GS      3
#define CHK     32
#define NCHK    (HH/CHK)        /* 32 */
#define LDA     36              /* floats per shared row */
#define TILE_FL (128*LDA)
#define STG_FL  (2*TILE_FL)
#define GSMEM_SZ (GS*STG_FL*4)  /* 110592 bytes */

__device__ __forceinline__ void mma_tf32(float* c, const unsigned* a, const unsigned* b) {
    asm volatile(
        "mma.sync.aligned.m16n8k8.row.col.f32.tf32.tf32.f32 "
        "{%0,%1,%2,%3}, {%4,%5,%6,%7}, {%8,%9}, {%0,%1,%2,%3};"
        : "+f"(c[0]), "+f"(c[1]), "+f"(c[2]), "+f"(c[3])
        : "r"(a[0]), "r"(a[1]), "r"(a[2]), "r"(a[3]), "r"(b[0]), "r"(b[1]));
}

__device__ __forceinline__ void load_chunk_g(const float* __restrict__ A,
                                             const float* __restrict__ Bm,
                                             float* sm, int stage,
                                             int row0, int col0, int kbase, int tid)
{
    float* sa = sm + stage*STG_FL;
    float* sb = sa + TILE_FL;
    #pragma unroll
    for (int it = 0; it < 4; ++it) {
        const int n   = tid + it*256;
        const int row = n >> 3;
        const int fc  = (n & 7) << 2;
        cp_async16(sa + row*LDA + fc, A  + (size_t)(row0 + row)*HH + kbase + fc);
        cp_async16(sb + row*LDA + fc, Bm + (size_t)(col0 + row)*HH + kbase + fc);
    }
    cp_async_commit();
}

__global__ __launch_bounds__(256) void gemm_tf32(const float* __restrict__ A,
                                                 const float* __restrict__ Bm,
                                                 float* __restrict__ C)
{
    extern __shared__ float sm[];
    const int tid  = threadIdx.x;
    const int wid  = tid >> 5;
    const int lane = tid & 31;
    const int wm   = wid & 1;
    const int wn   = wid >> 1;
    const int l4   = lane >> 2;
    const int lm   = lane & 3;
    const int row0 = blockIdx.y * 128;
    const int col0 = blockIdx.x * 128;

    float acc[4][4][4];
    #pragma unroll
    for (int mt = 0; mt < 4; ++mt)
        #pragma unroll
        for (int nt = 0; nt < 4; ++nt)
            #pragma unroll
            for (int r = 0; r < 4; ++r) acc[mt][nt][r] = 0.f;

    load_chunk_g(A, Bm, sm, 0, row0, col0, 0*CHK, tid);
    load_chunk_g(A, Bm, sm, 1, row0, col0, 1*CHK, tid);

    for (int c = 0; c < NCHK; ++c) {
        if (c + GS - 1 < NCHK)
            load_chunk_g(A, Bm, sm, (c + GS - 1) % GS, row0, col0, (c + GS - 1)*CHK, tid);

        if (c < NCHK - 2)       asm volatile("cp.async.wait_group 2;");
        else if (c == NCHK - 2) asm volatile("cp.async.wait_group 1;");
        else                    asm volatile("cp.async.wait_group 0;");
        __syncthreads();

        const float* sa = sm + (c % GS)*STG_FL;
        const float* sb = sa + TILE_FL;

        #pragma unroll
        for (int ks = 0; ks < 4; ++ks) {
            const int kk = ks*8;
            unsigned a[4][4], b[4][2];
            #pragma unroll
            for (int mt = 0; mt < 4; ++mt) {
                const float* ap = sa + (wm*64 + mt*16 + l4)*LDA + kk + lm;
                a[mt][0] = __float_as_uint(ap[0]);
                a[mt][1] = __float_as_uint(ap[8*LDA]);
                a[mt][2] = __float_as_uint(ap[4]);
                a[mt][3] = __float_as_uint(ap[8*LDA + 4]);
            }
            #pragma unroll
            for (int nt = 0; nt < 4; ++nt) {
                const float* bp = sb + (wn*32 + nt*8 + l4)*LDA + kk + lm;
                b[nt][0] = __float_as_uint(bp[0]);
                b[nt][1] = __float_as_uint(bp[4]);
            }
            #pragma unroll
            for (int mt = 0; mt < 4; ++mt)
                #pragma unroll
                for (int nt = 0; nt < 4; ++nt)
                    mma_tf32(acc[mt][nt], a[mt], b[nt]);
        }
        __syncthreads();
    }

    #pragma unroll
    for (int mt = 0; mt < 4; ++mt) {
        const int rg = row0 + wm*64 + mt*16 + l4;
        #pragma unroll
        for (int nt = 0; nt < 4; ++nt) {
            const int cg = col0 + wn*32 + nt*8 + lm*2;
            float* p = C + (size_t)rg*HH + cg;
            *(float2*)p            = make_float2(acc[mt][nt][0], acc[mt][nt][1]);
            *(float2*)(p + 8*HH)   = make_float2(acc[mt][nt][2], acc[mt][nt][3]);
        }
    }
}

// ---------------------------------------------------------------------------
// fused tf32 pre-rounding: x (8M floats) + 5 weight matrices (1M each).
// One launch; float4 per thread.
// ---------------------------------------------------------------------------
__global__ __launch_bounds__(256) void round_all(const float* __restrict__ x,
                                                 const float* __restrict__ Wq,
                                                 const float* __restrict__ Wk,
                                                 const float* __restrict__ Wv,
                                                 const float* __restrict__ Wg,
                                                 const float* __restrict__ Wo,
                                                 float* __restrict__ xr,
                                                 float* __restrict__ wr)
{
    const size_t XC = (size_t)MM*HH/4;       // float4 count of x
    const size_t WC = (size_t)HH*HH/4;       // float4 count per weight
    const size_t idx = (size_t)blockIdx.x * 256 + threadIdx.x;

    const float4* src;
    float4* dst;
    size_t off;
    if (idx < XC) {
        src = (const float4*)x; dst = (float4*)xr; off = idx;
    } else {
        const size_t r = idx - XC;
        const int w = (int)(r / WC);
        off = r % WC;
        const float* ws = (w == 0) ? Wq : (w == 1) ? Wk : (w == 2) ? Wv : (w == 3) ? Wg : Wo;
        src = (const float4*)ws;
        dst = (float4*)(wr + (size_t)w*HH*HH);
    }
    float4 v = src[off];
    v.x = to_tf32(v.x); v.y = to_tf32(v.y);
    v.z = to_tf32(v.z); v.w = to_tf32(v.w);
    dst[off] = v;
}

// ---------------------------------------------------------------------------
// alpha/beta: 8 tokens per block, weight rows register-resident per warp.
// ---------------------------------------------------------------------------
__global__ __launch_bounds__(256) void ab_kernel(const float* __restrict__ x,
                                                 const float* __restrict__ Wa,
                                                 const float* __restrict__ ba,
                                                 const float* __restrict__ Wb,
                                                 const float* __restrict__ bb,
                                                 float* __restrict__ ab)
{
    const int m0  = blockIdx.x * 8;
    const int tid = threadIdx.x;
    __shared__ float xs[8][HH];

    for (int n = tid; n < 8 * HH / 4; n += 256) {
        const int tok = n / (HH/4);
        const int e4  = (n % (HH/4)) * 4;
        *(float4*)&xs[tok][e4] = *(const float4*)&x[(size_t)(m0 + tok)*HH + e4];
    }
    __syncthreads();

    const int warp = tid >> 5, lane = tid & 31;
    for (int o = warp; o < 32; o += 8) {
        const float* w = (o < 16) ? (Wa + (size_t)o*HH) : (Wb + (size_t)(o-16)*HH);
        float wr[32];
        #pragma unroll
        for (int u = 0; u < 32; ++u) wr[u] = w[lane + u*32];
        const float bias = (o < 16) ? ba[o] : bb[o-16];
        for (int tok = 0; tok < 8; ++tok) {
            float sum = 0.f;
            #pragma unroll
            for (int u = 0; u < 32; ++u)
                sum = fmaf(wr[u], xs[tok][lane + u*32], sum);
            #pragma unroll
            for (int off = 16; off; off >>= 1)
                sum += __shfl_xor_sync(0xffffffffu, sum, off);
            if (lane == 0) {
                float y = sum + bias;
                ab[(size_t)(m0 + tok)*32 + o] = 1.f / (1.f + expf(-y));
            }
        }
    }
}

// ---------------------------------------------------------------------------
// activations: l2-normalize q and k per (token,head); silu(v) in place.
// ---------------------------------------------------------------------------
__global__ __launch_bounds__(256) void act_kernel(float* __restrict__ q,
                                                  float* __restrict__ k,
                                                  float* __restrict__ v)
{
    const int g    = blockIdx.x * 8 + (threadIdx.x >> 5);
    const int lane = threadIdx.x & 31;
    const size_t base = (size_t)g * HDD;

    {
        float a0 = q[base + lane], a1 = q[base + lane + 32];
        float ss = a0*a0 + a1*a1;
        #pragma unroll
        for (int off = 16; off; off >>= 1) ss += __shfl_xor_sync(0xffffffffu, ss, off);
        float inv = 1.f / fmaxf(sqrtf(ss), 1e-12f);
        q[base + lane] = a0 * inv;  q[base + lane + 32] = a1 * inv;
    }
    {
        float a0 = k[base + lane], a1 = k[base + lane + 32];
        float ss = a0*a0 + a1*a1;
        #pragma unroll
        for (int off = 16; off; off >>= 1) ss += __shfl_xor_sync(0xffffffffu, ss, off);
        float inv = 1.f / fmaxf(sqrtf(ss), 1e-12f);
        k[base + lane] = a0 * inv;  k[base + lane + 32] = a1 * inv;
    }
    {
        float a0 = v[base + lane], a1 = v[base + lane + 32];
        v[base + lane]      = a0 / (1.f + expf(-a0));
        v[base + lane + 32] = a1 / (1.f + expf(-a1));
    }
}

// ---------------------------------------------------------------------------
// Sequential scan, row-split: 2 blocks per (b,h), each owns 32 state rows x
// all 64 cols (out_i = sum_j s[i][j] q_j is row-local -> no cross-block comm).
// 256 threads: row i = half*32 + (tid>>3), col group c = tid&7 (8 cols = 4 f32x2).
// k/v/q staged 16 steps at a time via cp.async (double buffered); all alpha/beta
// staged once.
// ---------------------------------------------------------------------------
#define TILE 16
#define NTILE (SS/TILE)

__global__ __launch_bounds__(256) void scan_kernel(const float* __restrict__ q,
                                                   const float* __restrict__ k,
                                                   const float* __restrict__ v,
                                                   const float* __restrict__ ab,
                                                   float* __restrict__ attn)
{
    const int bh2  = blockIdx.x;          // 0..127
    const int b    = bh2 >> 5;
    const int h    = (bh2 >> 1) & 15;
    const int half = bh2 & 1;
    const int tid  = threadIdx.x;
    const int i    = half*32 + (tid >> 3);   // state row
    const int c    = tid & 7;                // col group (8 cols)

    __shared__ float sk[2][TILE][64];
    __shared__ float sv[2][TILE][64];
    __shared__ float sq[2][TILE][64];
    __shared__ float sab[SS][2];

    auto base = [&](int t) { return ((size_t)(b*SS + t) * HH + (size_t)h*HDD); };

    {
        const int tt = tid >> 4;
        const int e4 = (tid & 15) << 2;
        cp_async16(&sk[0][tt][e4], k + base(tt) + e4);
        cp_async16(&sv[0][tt][e4], v + base(tt) + e4);
        cp_async16(&sq[0][tt][e4], q + base(tt) + e4);
        cp_async_commit();
    }
    for (int t = tid; t < SS; t += 256) {
        const size_t o = (size_t)(b*SS + t) * 32;
        sab[t][0] = ab[o + h];
        sab[t][1] = ab[o + 16 + h];
    }
    cp_async_wait0();
    __syncthreads();

    ull s2[4];
    #pragma unroll
    for (int j = 0; j < 4; ++j) s2[j] = 0ull;

    int buf = 0;
    for (int tile = 0; tile < NTILE; ++tile) {
        const int t0 = tile * TILE;
        if (tile + 1 < NTILE) {
            const int nx = buf ^ 1;
            const int tt = tid >> 4;
            const int e4 = (tid & 15) << 2;
            const size_t nb = base(t0 + TILE + tt) + e4;
            cp_async16(&sk[nx][tt][e4], k + nb);
            cp_async16(&sv[nx][tt][e4], v + nb);
            cp_async16(&sq[nx][tt][e4], q + nb);
            cp_async_commit();
        }

        #pragma unroll 4
        for (int tt = 0; tt < TILE; ++tt) {
            const int t = t0 + tt;
            const float2 abv = *(const float2*)&sab[t][0];
            const float a  = abv.x;
            const float be = abv.y;
            const float ki = sk[buf][tt][i];
            const float vi = sv[buf][tt][i];

            const ull a2   = pk2(a, a);
            const ull be2  = pk2(be, be);
            const ull vi2  = pk2(vi, vi);
            const ull nki2 = pk2(-ki, -ki);

            ull k2[4], q2[4];
            {
                const ulonglong2* kp = (const ulonglong2*)&sk[buf][tt][c*8];
                const ulonglong2* qp = (const ulonglong2*)&sq[buf][tt][c*8];
                ulonglong2 kk0 = kp[0], kk1 = kp[1];
                ulonglong2 qq0 = qp[0], qq1 = qp[1];
                k2[0] = kk0.x; k2[1] = kk0.y; k2[2] = kk1.x; k2[3] = kk1.y;
                q2[0] = qq0.x; q2[1] = qq0.y; q2[2] = qq1.x; q2[3] = qq1.y;
            }

            ull pa = 0ull, pb = 0ull;
            #pragma unroll
            for (int j = 0; j < 4; ++j) {
                const ull w2  = mul2(be2, k2[j]);
                const ull r   = mul2(a2, s2[j]);
                const ull tmp = fma2(nki2, r, vi2);
                s2[j] = fma2(w2, tmp, r);
                if (j & 1) pb = fma2(s2[j], q2[j], pb);
                else       pa = fma2(s2[j], q2[j], pa);
            }
            const float2 ps = upk2(add2(pa, pb));
            float partial = ps.x + ps.y;
            partial += __shfl_xor_sync(0xffffffffu, partial, 1);
            partial += __shfl_xor_sync(0xffffffffu, partial, 2);
            partial += __shfl_xor_sync(0xffffffffu, partial, 4);
            if (c == 0) attn[base(t) + i] = partial;
        }

        if (tile + 1 < NTILE) cp_async_wait0();
        __syncthreads();
        buf ^= 1;
    }
}

// ---------------------------------------------------------------------------
// layernorm over H + gate; output pre-rounded to tf32 (feeds the Wo GEMM)
// ---------------------------------------------------------------------------
__global__ __launch_bounds__(256) void ln_gate_kernel(const float* __restrict__ attn,
                                                      const float* __restrict__ gate,
                                                      const float* __restrict__ ln_g,
                                                      const float* __restrict__ ln_b,
                                                      float* __restrict__ z)
{
    const int m   = blockIdx.x;
    const int tid = threadIdx.x;
    const size_t rb = (size_t)m * HH + tid*4;

    float4 xv = *(const float4*)&attn[rb];
    float s  = xv.x + xv.y + xv.z + xv.w;
    float ss = xv.x*xv.x + xv.y*xv.y + xv.z*xv.z + xv.w*xv.w;
    #pragma unroll
    for (int off = 16; off; off >>= 1) {
        s  += __shfl_xor_sync(0xffffffffu, s,  off);
        ss += __shfl_xor_sync(0xffffffffu, ss, off);
    }
    __shared__ float rs[8], rss[8];
    if ((tid & 31) == 0) { rs[tid>>5] = s; rss[tid>>5] = ss; }
    __syncthreads();
    float tot = 0.f, tots = 0.f;
    #pragma unroll
    for (int w = 0; w < 8; ++w) { tot += rs[w]; tots += rss[w]; }

    const float mean = tot * (1.f/HH);
    const float var  = tots * (1.f/HH) - mean*mean;
    const float inv  = rsqrtf(var + 1e-5f);

    float4 gv = *(const float4*)&gate[rb];
    float4 lg = *(const float4*)&ln_g[tid*4];
    float4 lb = *(const float4*)&ln_b[tid*4];

    float4 o;
    o.x = to_tf32(((xv.x-mean)*inv*lg.x + lb.x) * (gv.x / (1.f + expf(-gv.x))));
    o.y = to_tf32(((xv.y-mean)*inv*lg.y + lb.y) * (gv.y / (1.f + expf(-gv.y))));
    o.z = to_tf32(((xv.z-mean)*inv*lg.z + lb.z) * (gv.z / (1.f + expf(-gv.z))));
    o.w = to_tf32(((xv.w-mean)*inv*lg.w + lb.w) * (gv.w / (1.f + expf(-gv.w))));
    *(float4*)&z[rb] = o;
}

// ---------------------------------------------------------------------------
extern "C" void kernel_launch(void* const* d_in, const int* in_sizes, int n_in,
                              void* d_out, int out_size)
{
    const float* x    = (const float*)d_in[0];
    const float* Wq   = (const float*)d_in[1];
    const float* Wk   = (const float*)d_in[2];
    const float* Wv   = (const float*)d_in[3];
    const float* Wa   = (const float*)d_in[4];
    const float* ba   = (const float*)d_in[5];
    const float* Wb   = (const float*)d_in[6];
    const float* bb   = (const float*)d_in[7];
    const float* Wg   = (const float*)d_in[8];
    const float* Wo   = (const float*)d_in[9];
    const float* ln_g = (const float*)d_in[10];
    const float* ln_b = (const float*)d_in[11];
    float* out = (float*)d_out;

    float *qp, *kp, *vp, *gp, *abp, *attnp, *zp, *xrp, *wrp;
    cudaGetSymbolAddress((void**)&qp,    g_q);
    cudaGetSymbolAddress((void**)&kp,    g_k);
    cudaGetSymbolAddress((void**)&vp,    g_v);
    cudaGetSymbolAddress((void**)&gp,    g_g);
    cudaGetSymbolAddress((void**)&abp,   g_ab);
    cudaGetSymbolAddress((void**)&attnp, g_attn);
    cudaGetSymbolAddress((void**)&zp,    g_z);
    cudaGetSymbolAddress((void**)&xrp,   g_xr);
    cudaGetSymbolAddress((void**)&wrp,   g_wr);

    float* wq_r = wrp + 0*(size_t)HH*HH;
    float* wk_r = wrp + 1*(size_t)HH*HH;
    float* wv_r = wrp + 2*(size_t)HH*HH;
    float* wg_r = wrp + 3*(size_t)HH*HH;
    float* wo_r = wrp + 4*(size_t)HH*HH;

    cudaFuncSetAttribute(gemm_tf32, cudaFuncAttributeMaxDynamicSharedMemorySize, GSMEM_SZ);

    dim3 grid_g(HH/128, MM/128);   // (8, 64)
    const int round_blocks = (MM*HH + 5*HH*HH) / (4*256);   // 13312

    // launch 0: fused tf32 rounding
    round_all<<<round_blocks, 256>>>(x, Wq, Wk, Wv, Wg, Wo, xrp, wrp);
    // launch 1: alpha/beta (independent of rounding/gemms)
    ab_kernel<<<MM/8, 256>>>(x, Wa, ba, Wb, bb, abp);
    // launches 2-5: projections (ncu -s 5 -c 1 captures launch 5 = gemm_tf32)
    gemm_tf32<<<grid_g, 256, GSMEM_SZ>>>(xrp, wq_r, qp);
    gemm_tf32<<<grid_g, 256, GSMEM_SZ>>>(xrp, wk_r, kp);
    gemm_tf32<<<grid_g, 256, GSMEM_SZ>>>(xrp, wv_r, vp);
    gemm_tf32<<<grid_g, 256, GSMEM_SZ>>>(xrp, wg_r, gp);

    act_kernel<<<(MM*NHH)/8, 256>>>(qp, kp, vp);

    scan_kernel<<<2*BB*NHH, 256>>>(qp, kp, vp, abp, attnp);

    ln_gate_kernel<<<MM, 256>>>(attnp, gp, ln_g, ln_b, zp);

    gemm_tf32<<<grid_g, 256, GSMEM_SZ>>>(zp, wo_r, out);
}

// round 7
// speedup vs baseline: 3.2057x; 1.0772x over previous
#include <cuda_runtime.h>
#include <math.h>

#define BB   4
#define SS   2048
#define HH   1024
#define NHH  16
#define HDD  64
#define MM   (BB*SS)   /* 8192 tokens */
#define PW   4096      /* packed proj width: q|k|v|g */

// ---------------- scratch (device globals: allocation-free) ----------------
__device__ float g_proj[(size_t)MM*PW];      // packed q|k|v|g, row stride 4096
__device__ float g_ab[(size_t)MM*2*NHH];
__device__ float g_attn[(size_t)MM*HH];
__device__ float g_z[(size_t)MM*HH];
__device__ float g_xr[(size_t)MM*HH];        // tf32-rounded x
__device__ float g_wr[(size_t)5*HH*HH];      // tf32-rounded Wq,Wk,Wv,Wg,Wo (rows concat)

// ---------------------------------------------------------------------------
// packed f32x2 helpers
// ---------------------------------------------------------------------------
typedef unsigned long long ull;
__device__ __forceinline__ ull pk2(float x, float y) {
    ull r; asm("mov.b64 %0, {%1,%2};" : "=l"(r) : "f"(x), "f"(y)); return r;
}
__device__ __forceinline__ ull mul2(ull a, ull b) {
    ull d; asm("mul.rn.f32x2 %0, %1, %2;" : "=l"(d) : "l"(a), "l"(b)); return d;
}
__device__ __forceinline__ ull add2(ull a, ull b) {
    ull d; asm("add.rn.f32x2 %0, %1, %2;" : "=l"(d) : "l"(a), "l"(b)); return d;
}
__device__ __forceinline__ ull fma2(ull a, ull b, ull c) {
    ull d; asm("fma.rn.f32x2 %0, %1, %2, %3;" : "=l"(d) : "l"(a), "l"(b), "l"(c)); return d;
}
__device__ __forceinline__ float2 upk2(ull a) {
    float2 f; asm("mov.b64 {%0,%1}, %2;" : "=f"(f.x), "=f"(f.y) : "l"(a)); return f;
}

__device__ __forceinline__ void cp_async16(void* dst_smem, const void* src_gmem) {
    unsigned dst = (unsigned)__cvta_generic_to_shared(dst_smem);
    asm volatile("cp.async.cg.shared.global [%0], [%1], 16;\n" :: "r"(dst), "l"(src_gmem));
}
__device__ __forceinline__ void cp_async_commit() {
    asm volatile("cp.async.commit_group;\n");
}
__device__ __forceinline__ void cp_async_wait0() {
    asm volatile("cp.async.wait_group 0;\n");
}

__device__ __forceinline__ float to_tf32(float x) {
    unsigned u; asm("cvt.rna.tf32.f32 %0, %1;" : "=r"(u) : "f"(x));
    return __uint_as_float(u);
}

// ---------------------------------------------------------------------------
// tf32 tensor-core GEMM via mma.sync: C[M,N] = A[M,K=1024] @ B[N,K]^T.
// Block tile 128x128, K-chunks of 32, 3-stage cp.async ring, 8 warps (2m x 4n),
// warp tile 64x32 = 4x4 m16n8k8. Fragment double-buffer across ks-steps.
// ---------------------------------------------------------------------------
#define GS      3
#define CHK     32
#define NCHK    (HH/CHK)        /* 32 */
#define LDA     36
#define TILE_FL (128*LDA)
#define STG_FL  (2*TILE_FL)
#define GSMEM_SZ (GS*STG_FL*4)  /* 110592 bytes */

__device__ __forceinline__ void mma_tf32(float* c, const unsigned* a, const unsigned* b) {
    asm volatile(
        "mma.sync.aligned.m16n8k8.row.col.f32.tf32.tf32.f32 "
        "{%0,%1,%2,%3}, {%4,%5,%6,%7}, {%8,%9}, {%0,%1,%2,%3};"
        : "+f"(c[0]), "+f"(c[1]), "+f"(c[2]), "+f"(c[3])
        : "r"(a[0]), "r"(a[1]), "r"(a[2]), "r"(a[3]), "r"(b[0]), "r"(b[1]));
}

__device__ __forceinline__ void load_chunk_g(const float* __restrict__ A,
                                             const float* __restrict__ Bm,
                                             float* sm, int stage,
                                             int row0, int col0, int kbase, int tid)
{
    float* sa = sm + stage*STG_FL;
    float* sb = sa + TILE_FL;
    #pragma unroll
    for (int it = 0; it < 4; ++it) {
        const int n   = tid + it*256;
        const int row = n >> 3;
        const int fc  = (n & 7) << 2;
        cp_async16(sa + row*LDA + fc, A  + (size_t)(row0 + row)*HH + kbase + fc);
        cp_async16(sb + row*LDA + fc, Bm + (size_t)(col0 + row)*HH + kbase + fc);
    }
    cp_async_commit();
}

__global__ __launch_bounds__(256, 2) void gemm_tf32(const float* __restrict__ A,
                                                    const float* __restrict__ Bm,
                                                    float* __restrict__ C,
                                                    int ldc)
{
    extern __shared__ float sm[];
    const int tid  = threadIdx.x;
    const int wid  = tid >> 5;
    const int lane = tid & 31;
    const int wm   = wid & 1;
    const int wn   = wid >> 1;
    const int l4   = lane >> 2;
    const int lm   = lane & 3;
    const int row0 = blockIdx.y * 128;
    const int col0 = blockIdx.x * 128;

    float acc[4][4][4];
    #pragma unroll
    for (int mt = 0; mt < 4; ++mt)
        #pragma unroll
        for (int nt = 0; nt < 4; ++nt)
            #pragma unroll
            for (int r = 0; r < 4; ++r) acc[mt][nt][r] = 0.f;

    load_chunk_g(A, Bm, sm, 0, row0, col0, 0*CHK, tid);
    load_chunk_g(A, Bm, sm, 1, row0, col0, 1*CHK, tid);

    for (int c = 0; c < NCHK; ++c) {
        if (c + GS - 1 < NCHK)
            load_chunk_g(A, Bm, sm, (c + GS - 1) % GS, row0, col0, (c + GS - 1)*CHK, tid);

        if (c < NCHK - 2)       asm volatile("cp.async.wait_group 2;");
        else if (c == NCHK - 2) asm volatile("cp.async.wait_group 1;");
        else                    asm volatile("cp.async.wait_group 0;");
        __syncthreads();

        const float* sa = sm + (c % GS)*STG_FL;
        const float* sb = sa + TILE_FL;

        unsigned a[2][4][4], b[2][4][2];

        // load fragments for ks=0
        #pragma unroll
        for (int mt = 0; mt < 4; ++mt) {
            const float* ap = sa + (wm*64 + mt*16 + l4)*LDA + lm;
            a[0][mt][0] = __float_as_uint(ap[0]);
            a[0][mt][1] = __float_as_uint(ap[8*LDA]);
            a[0][mt][2] = __float_as_uint(ap[4]);
            a[0][mt][3] = __float_as_uint(ap[8*LDA + 4]);
        }
        #pragma unroll
        for (int nt = 0; nt < 4; ++nt) {
            const float* bp = sb + (wn*32 + nt*8 + l4)*LDA + lm;
            b[0][nt][0] = __float_as_uint(bp[0]);
            b[0][nt][1] = __float_as_uint(bp[4]);
        }

        #pragma unroll
        for (int ks = 0; ks < 4; ++ks) {
            const int cur = ks & 1, nxt = cur ^ 1;
            if (ks < 3) {
                const int kk = (ks + 1)*8;
                #pragma unroll
                for (int mt = 0; mt < 4; ++mt) {
                    const float* ap = sa + (wm*64 + mt*16 + l4)*LDA + kk + lm;
                    a[nxt][mt][0] = __float_as_uint(ap[0]);
                    a[nxt][mt][1] = __float_as_uint(ap[8*LDA]);
                    a[nxt][mt][2] = __float_as_uint(ap[4]);
                    a[nxt][mt][3] = __float_as_uint(ap[8*LDA + 4]);
                }
                #pragma unroll
                for (int nt = 0; nt < 4; ++nt) {
                    const float* bp = sb + (wn*32 + nt*8 + l4)*LDA + kk + lm;
                    b[nxt][nt][0] = __float_as_uint(bp[0]);
                    b[nxt][nt][1] = __float_as_uint(bp[4]);
                }
            }
            #pragma unroll
            for (int mt = 0; mt < 4; ++mt)
                #pragma unroll
                for (int nt = 0; nt < 4; ++nt)
                    mma_tf32(acc[mt][nt], a[cur][mt], b[cur][nt]);
        }
        __syncthreads();
    }

    #pragma unroll
    for (int mt = 0; mt < 4; ++mt) {
        const int rg = row0 + wm*64 + mt*16 + l4;
        #pragma unroll
        for (int nt = 0; nt < 4; ++nt) {
            const int cg = col0 + wn*32 + nt*8 + lm*2;
            float* p = C + (size_t)rg*ldc + cg;
            *(float2*)p            = make_float2(acc[mt][nt][0], acc[mt][nt][1]);
            *(float2*)(p + 8*ldc)  = make_float2(acc[mt][nt][2], acc[mt][nt][3]);
        }
    }
}

// ---------------------------------------------------------------------------
// fused tf32 pre-rounding: x + 5 weights
// ---------------------------------------------------------------------------
__global__ __launch_bounds__(256) void round_all(const float* __restrict__ x,
                                                 const float* __restrict__ Wq,
                                                 const float* __restrict__ Wk,
                                                 const float* __restrict__ Wv,
                                                 const float* __restrict__ Wg,
                                                 const float* __restrict__ Wo,
                                                 float* __restrict__ xr,
                                                 float* __restrict__ wr)
{
    const size_t XC = (size_t)MM*HH/4;
    const size_t WC = (size_t)HH*HH/4;
    const size_t idx = (size_t)blockIdx.x * 256 + threadIdx.x;

    const float4* src;
    float4* dst;
    size_t off;
    if (idx < XC) {
        src = (const float4*)x; dst = (float4*)xr; off = idx;
    } else {
        const size_t r = idx - XC;
        const int w = (int)(r / WC);
        off = r % WC;
        const float* ws = (w == 0) ? Wq : (w == 1) ? Wk : (w == 2) ? Wv : (w == 3) ? Wg : Wo;
        src = (const float4*)ws;
        dst = (float4*)(wr + (size_t)w*HH*HH);
    }
    float4 v = src[off];
    v.x = to_tf32(v.x); v.y = to_tf32(v.y);
    v.z = to_tf32(v.z); v.w = to_tf32(v.w);
    dst[off] = v;
}

// ---------------------------------------------------------------------------
// alpha/beta: 8 tokens per block, weight rows register-resident per warp.
// ---------------------------------------------------------------------------
__global__ __launch_bounds__(256) void ab_kernel(const float* __restrict__ x,
                                                 const float* __restrict__ Wa,
                                                 const float* __restrict__ ba,
                                                 const float* __restrict__ Wb,
                                                 const float* __restrict__ bb,
                                                 float* __restrict__ ab)
{
    const int m0  = blockIdx.x * 8;
    const int tid = threadIdx.x;
    __shared__ float xs[8][HH];

    for (int n = tid; n < 8 * HH / 4; n += 256) {
        const int tok = n / (HH/4);
        const int e4  = (n % (HH/4)) * 4;
        *(float4*)&xs[tok][e4] = *(const float4*)&x[(size_t)(m0 + tok)*HH + e4];
    }
    __syncthreads();

    const int warp = tid >> 5, lane = tid & 31;
    for (int o = warp; o < 32; o += 8) {
        const float* w = (o < 16) ? (Wa + (size_t)o*HH) : (Wb + (size_t)(o-16)*HH);
        float wr[32];
        #pragma unroll
        for (int u = 0; u < 32; ++u) wr[u] = w[lane + u*32];
        const float bias = (o < 16) ? ba[o] : bb[o-16];
        for (int tok = 0; tok < 8; ++tok) {
            float sum = 0.f;
            #pragma unroll
            for (int u = 0; u < 32; ++u)
                sum = fmaf(wr[u], xs[tok][lane + u*32], sum);
            #pragma unroll
            for (int off = 16; off; off >>= 1)
                sum += __shfl_xor_sync(0xffffffffu, sum, off);
            if (lane == 0) {
                float y = sum + bias;
                ab[(size_t)(m0 + tok)*32 + o] = 1.f / (1.f + expf(-y));
            }
        }
    }
}

// ---------------------------------------------------------------------------
// act_qk: l2-normalize q and k per (token,head) inside packed proj.
// one warp per (token,head) group.
// ---------------------------------------------------------------------------
__global__ __launch_bounds__(256) void act_qk(float* __restrict__ proj)
{
    const int g    = blockIdx.x * 8 + (threadIdx.x >> 5);
    const int lane = threadIdx.x & 31;
    const int tok  = g >> 4;
    const int h    = g & 15;
    const size_t base = (size_t)tok*PW + h*HDD;

    {
        float* q = proj + base;
        float a0 = q[lane], a1 = q[lane + 32];
        float ss = a0*a0 + a1*a1;
        #pragma unroll
        for (int off = 16; off; off >>= 1) ss += __shfl_xor_sync(0xffffffffu, ss, off);
        float inv = 1.f / fmaxf(sqrtf(ss), 1e-12f);
        q[lane] = a0 * inv;  q[lane + 32] = a1 * inv;
    }
    {
        float* k = proj + base + HH;
        float a0 = k[lane], a1 = k[lane + 32];
        float ss = a0*a0 + a1*a1;
        #pragma unroll
        for (int off = 16; off; off >>= 1) ss += __shfl_xor_sync(0xffffffffu, ss, off);
        float inv = 1.f / fmaxf(sqrtf(ss), 1e-12f);
        k[lane] = a0 * inv;  k[lane + 32] = a1 * inv;
    }
}

// ---------------------------------------------------------------------------
// act_v: silu over v region of packed proj (float4 per thread)
// ---------------------------------------------------------------------------
__global__ __launch_bounds__(256) void act_v(float* __restrict__ proj)
{
    const size_t idx = (size_t)blockIdx.x * 256 + threadIdx.x;  // over MM*256 float4
    const size_t m   = idx >> 8;
    const size_t c4  = idx & 255;
    float4* p = (float4*)proj + m*(PW/4) + (2*HH/4) + c4;
    float4 v = *p;
    v.x = v.x / (1.f + expf(-v.x));
    v.y = v.y / (1.f + expf(-v.y));
    v.z = v.z / (1.f + expf(-v.z));
    v.w = v.w / (1.f + expf(-v.w));
    *p = v;
}

// ---------------------------------------------------------------------------
// Sequential scan, row-split, shuffle-free. 2 blocks per (b,h), each owns 32
// state rows. 256 threads: row r = tid>>3 (0..31), col group c = tid&7.
// Per step: state update + scalar partial -> STS (addr = tid, conflict-free).
// Per 16-step tile: cooperative reduce of 8 partials/output from shared,
// coalesced float2 stores to attn. No shuffles anywhere in the hot loop.
// ---------------------------------------------------------------------------
#define TILE 16
#define NTILE (SS/TILE)
// dynamic smem layout (floats):
#define SC_K(bufi)   ((bufi)*TILE*64)                 /* 2 bufs k */
#define SC_V(bufi)   (2*TILE*64 + (bufi)*TILE*64)
#define SC_Q(bufi)   (4*TILE*64 + (bufi)*TILE*64)
#define SC_AB        (6*TILE*64)                      /* SS*2 floats */
#define SC_PART      (6*TILE*64 + SS*2)               /* TILE*32*8 floats */
#define SCAN_SMEM_FL (6*TILE*64 + SS*2 + TILE*32*8)
#define SCAN_SMEM_SZ (SCAN_SMEM_FL*4)                 /* 57344 bytes */

__global__ __launch_bounds__(256) void scan_kernel(const float* __restrict__ proj,
                                                   const float* __restrict__ ab,
                                                   float* __restrict__ attn)
{
    extern __shared__ float sh[];
    const int bh2  = blockIdx.x;          // 0..127
    const int b    = bh2 >> 5;
    const int h    = (bh2 >> 1) & 15;
    const int half = bh2 & 1;
    const int tid  = threadIdx.x;
    const int i    = half*32 + (tid >> 3);   // state row 0..63
    const int c    = tid & 7;                // col group (8 cols)

    const float* q = proj;            // +0
    const float* k = proj + HH;       // +1024
    const float* v = proj + 2*HH;     // +2048

    auto base = [&](int t) { return ((size_t)(b*SS + t) * PW + (size_t)h*HDD); };
    auto abase = [&](int t) { return ((size_t)(b*SS + t) * HH + (size_t)h*HDD); };

    {
        const int tt = tid >> 4;
        const int e4 = (tid & 15) << 2;
        cp_async16(&sh[SC_K(0) + tt*64 + e4], k + base(tt) + e4);
        cp_async16(&sh[SC_V(0) + tt*64 + e4], v + base(tt) + e4);
        cp_async16(&sh[SC_Q(0) + tt*64 + e4], q + base(tt) + e4);
        cp_async_commit();
    }
    for (int t = tid; t < SS; t += 256) {
        const size_t o = (size_t)(b*SS + t) * 32;
        sh[SC_AB + t*2 + 0] = ab[o + h];
        sh[SC_AB + t*2 + 1] = ab[o + 16 + h];
    }
    cp_async_wait0();
    __syncthreads();

    ull s2[4];
    #pragma unroll
    for (int j = 0; j < 4; ++j) s2[j] = 0ull;

    int buf = 0;
    for (int tile = 0; tile < NTILE; ++tile) {
        const int t0 = tile * TILE;
        if (tile + 1 < NTILE) {
            const int nx = buf ^ 1;
            const int tt = tid >> 4;
            const int e4 = (tid & 15) << 2;
            const size_t nb = base(t0 + TILE + tt) + e4;
            cp_async16(&sh[SC_K(nx) + tt*64 + e4], k + nb);
            cp_async16(&sh[SC_V(nx) + tt*64 + e4], v + nb);
            cp_async16(&sh[SC_Q(nx) + tt*64 + e4], q + nb);
            cp_async_commit();
        }

        const float* skb = &sh[SC_K(buf)];
        const float* svb = &sh[SC_V(buf)];
        const float* sqb = &sh[SC_Q(buf)];

        #pragma unroll 4
        for (int tt = 0; tt < TILE; ++tt) {
            const int t = t0 + tt;
            const float2 abv = *(const float2*)&sh[SC_AB + t*2];
            const float a  = abv.x;
            const float be = abv.y;
            const float ki = skb[tt*64 + i];
            const float vi = svb[tt*64 + i];

            const ull a2   = pk2(a, a);
            const ull be2  = pk2(be, be);
            const ull vi2  = pk2(vi, vi);
            const ull nki2 = pk2(-ki, -ki);

            ull k2[4], q2[4];
            {
                const ulonglong2* kp = (const ulonglong2*)&skb[tt*64 + c*8];
                const ulonglong2* qp = (const ulonglong2*)&sqb[tt*64 + c*8];
                ulonglong2 kk0 = kp[0], kk1 = kp[1];
                ulonglong2 qq0 = qp[0], qq1 = qp[1];
                k2[0] = kk0.x; k2[1] = kk0.y; k2[2] = kk1.x; k2[3] = kk1.y;
                q2[0] = qq0.x; q2[1] = qq0.y; q2[2] = qq1.x; q2[3] = qq1.y;
            }

            ull pa = 0ull, pb = 0ull;
            #pragma unroll
            for (int j = 0; j < 4; ++j) {
                const ull w2  = mul2(be2, k2[j]);
                const ull r   = mul2(a2, s2[j]);
                const ull tmp = fma2(nki2, r, vi2);
                s2[j] = fma2(w2, tmp, r);
                if (j & 1) pb = fma2(s2[j], q2[j], pb);
                else       pa = fma2(s2[j], q2[j], pa);
            }
            const float2 ps = upk2(add2(pa, pb));
            sh[SC_PART + tt*256 + tid] = ps.x + ps.y;
        }
        __syncthreads();

        // tile reduction: thread -> (step tt = tid>>4, rows r2, r2+1)
        {
            const int tt = tid >> 4;
            const int r2 = (tid & 15) << 1;
            const float* p0 = &sh[SC_PART + tt*256 + r2*8];
            float4 u0 = *(const float4*)(p0);
            float4 u1 = *(const float4*)(p0 + 4);
            float4 u2 = *(const float4*)(p0 + 8);
            float4 u3 = *(const float4*)(p0 + 12);
            float o0 = (u0.x+u0.y)+(u0.z+u0.w) + (u1.x+u1.y)+(u1.z+u1.w);
            float o1 = (u2.x+u2.y)+(u2.z+u2.w) + (u3.x+u3.y)+(u3.z+u3.w);
            *(float2*)&attn[abase(t0 + tt) + half*32 + r2] = make_float2(o0, o1);
        }

        if (tile + 1 < NTILE) cp_async_wait0();
        __syncthreads();
        buf ^= 1;
    }
}

// ---------------------------------------------------------------------------
// layernorm over H + gate (gate read from packed proj); z pre-rounded to tf32
// ---------------------------------------------------------------------------
__global__ __launch_bounds__(256) void ln_gate_kernel(const float* __restrict__ attn,
                                                      const float* __restrict__ proj,
                                                      const float* __restrict__ ln_g,
                                                      const float* __restrict__ ln_b,
                                                      float* __restrict__ z)
{
    const int m   = blockIdx.x;
    const int tid = threadIdx.x;
    const size_t rb = (size_t)m * HH + tid*4;

    float4 xv = *(const float4*)&attn[rb];
    float s  = xv.x + xv.y + xv.z + xv.w;
    float ss = xv.x*xv.x + xv.y*xv.y + xv.z*xv.z + xv.w*xv.w;
    #pragma unroll
    for (int off = 16; off; off >>= 1) {
        s  += __shfl_xor_sync(0xffffffffu, s,  off);
        ss += __shfl_xor_sync(0xffffffffu, ss, off);
    }
    __shared__ float rs[8], rss[8];
    if ((tid & 31) == 0) { rs[tid>>5] = s; rss[tid>>5] = ss; }
    __syncthreads();
    float tot = 0.f, tots = 0.f;
    #pragma unroll
    for (int w = 0; w < 8; ++w) { tot += rs[w]; tots += rss[w]; }

    const float mean = tot * (1.f/HH);
    const float var  = tots * (1.f/HH) - mean*mean;
    const float inv  = rsqrtf(var + 1e-5f);

    float4 gv = *(const float4*)&proj[(size_t)m*PW + 3*HH + tid*4];
    float4 lg = *(const float4*)&ln_g[tid*4];
    float4 lb = *(const float4*)&ln_b[tid*4];

    float4 o;
    o.x = to_tf32(((xv.x-mean)*inv*lg.x + lb.x) * (gv.x / (1.f + expf(-gv.x))));
    o.y = to_tf32(((xv.y-mean)*inv*lg.y + lb.y) * (gv.y / (1.f + expf(-gv.y))));
    o.z = to_tf32(((xv.z-mean)*inv*lg.z + lb.z) * (gv.z / (1.f + expf(-gv.z))));
    o.w = to_tf32(((xv.w-mean)*inv*lg.w + lb.w) * (gv.w / (1.f + expf(-gv.w))));
    *(float4*)&z[rb] = o;
}

// ---------------------------------------------------------------------------
extern "C" void kernel_launch(void* const* d_in, const int* in_sizes, int n_in,
                              void* d_out, int out_size)
{
    const float* x    = (const float*)d_in[0];
    const float* Wq   = (const float*)d_in[1];
    const float* Wk   = (const float*)d_in[2];
    const float* Wv   = (const float*)d_in[3];
    const float* Wa   = (const float*)d_in[4];
    const float* ba   = (const float*)d_in[5];
    const float* Wb   = (const float*)d_in[6];
    const float* bb   = (const float*)d_in[7];
    const float* Wg   = (const float*)d_in[8];
    const float* Wo   = (const float*)d_in[9];
    const float* ln_g = (const float*)d_in[10];
    const float* ln_b = (const float*)d_in[11];
    float* out = (float*)d_out;

    float *projp, *abp, *attnp, *zp, *xrp, *wrp;
    cudaGetSymbolAddress((void**)&projp, g_proj);
    cudaGetSymbolAddress((void**)&abp,   g_ab);
    cudaGetSymbolAddress((void**)&attnp, g_attn);
    cudaGetSymbolAddress((void**)&zp,    g_z);
    cudaGetSymbolAddress((void**)&xrp,   g_xr);
    cudaGetSymbolAddress((void**)&wrp,   g_wr);

    float* wo_r = wrp + 4*(size_t)HH*HH;

    cudaFuncSetAttribute(gemm_tf32, cudaFuncAttributeMaxDynamicSharedMemorySize, GSMEM_SZ);
    cudaFuncSetAttribute(scan_kernel, cudaFuncAttributeMaxDynamicSharedMemorySize, SCAN_SMEM_SZ);

    const int round_blocks = (MM*HH + 5*HH*HH) / (4*256);

    // 0: fused tf32 rounding
    round_all<<<round_blocks, 256>>>(x, Wq, Wk, Wv, Wg, Wo, xrp, wrp);
    // 1: alpha/beta
    ab_kernel<<<MM/8, 256>>>(x, Wa, ba, Wb, bb, abp);
    // 2: fused QKVG projection (N=4096; weights rows 0..4095 = Wq|Wk|Wv|Wg)
    dim3 grid_qkvg(PW/128, MM/128);   // (32, 64)
    gemm_tf32<<<grid_qkvg, 256, GSMEM_SZ>>>(xrp, wrp, projp, PW);
    // 3: q/k l2norm   4: v silu
    act_qk<<<(MM*NHH)/8, 256>>>(projp);
    act_v<<<MM, 256>>>(projp);
    // 5: scan (profiled by ncu -s 5 -c 1)
    scan_kernel<<<2*BB*NHH, 256, SCAN_SMEM_SZ>>>(projp, abp, attnp);
    // 6: LN + gate
    ln_gate_kernel<<<MM, 256>>>(attnp, projp, ln_g, ln_b, zp);
    // 7: output projection
    dim3 grid_o(HH/128, MM/128);      // (8, 64)
    gemm_tf32<<<grid_o, 256, GSMEM_SZ>>>(zp, wo_r, out, HH);
}